// round 15
// baseline (speedup 1.0000x reference)
#include <cuda_runtime.h>
#include <cuda_fp16.h>
#include <cstdint>

// Problem constants
#define BB    8
#define SS    256
#define DIMQ  64
#define DD    100
#define SA    255   // rows of a2
#define SO    254   // output rows
#define TEMP_INV 0.1f
#define EPSV  1e-5f

// GEMM tiling per (b, i, jtile): D[j=128, d=104] = A[j,k] * B[d,k], K padded 200->224 (int8 k32)
#define NPAD  104
#define KK    200
#define NT    13      // 104/8 n-tiles
#define KS32  7       // 224/32 k-steps
#define KW    56      // data words per row (224 bytes / 4)
#define RSTR  60      // smem row stride in u32 words; 60%32=28 -> conflict-free frag loads
#define CSTR  106     // even -> 8B-aligned float2 staging rows; fits under 13920 words

// Scratch (device globals: no allocation allowed)
__device__ float g_Q1[BB*SS*DD];            // [b][i][d]
__device__ float g_K1T[BB*DD*SS];           // [b][c][j]
__device__ float g_P0[BB*SS*SS];            // conv3 partial, h=0 tap
__device__ float g_P1[BB*SS*SS];            // conv3 partial, h=1 tap
__device__ uint32_t g_Bq[NPAD*KW];          // W2 quantized s8, packed words [d][k/4]
__device__ float g_Ud[NPAD];                // per-d B dequant scales
__device__ unsigned g_K1mxE[BB*DD];         // encoded per-(b,c) max of K1
__device__ unsigned g_K1mnE[BB*DD];         // encoded per-(b,c) min of K1
__device__ float g_WqT[2*DIMQ*DD];          // W1 q-branch transposed: [t2][d] (t2=0..127)
__device__ float g_WkT[DIMQ*DD];            // W1 k-branch taps summed, transposed: [t][d]
__device__ float g_A1f[DD], g_C1f[DD], g_A2f[DD], g_C2f[DD], g_b12[DD];

// ---------------- helpers ----------------
__device__ __forceinline__ unsigned fenc(float f) {
    unsigned u = __float_as_uint(f);
    return (u & 0x80000000u) ? ~u : (u | 0x80000000u);
}
__device__ __forceinline__ float fdec(unsigned u) {
    unsigned v = (u & 0x80000000u) ? (u & 0x7fffffffu) : ~u;
    return __uint_as_float(v);
}
__device__ __forceinline__ void mma_u8s8(int* c, uint32_t a0, uint32_t a1, uint32_t a2,
                                         uint32_t a3, uint32_t b0, uint32_t b1) {
    asm volatile(
        "mma.sync.aligned.m16n8k32.row.col.s32.u8.s8.s32 "
        "{%0,%1,%2,%3}, {%4,%5,%6,%7}, {%8,%9}, {%0,%1,%2,%3};"
        : "+r"(c[0]), "+r"(c[1]), "+r"(c[2]), "+r"(c[3])
        : "r"(a0), "r"(a1), "r"(a2), "r"(a3), "r"(b0), "r"(b1));
}

// ============================================================
// Kernel 0: params — bn folds, W2 int8 quant, W1 transposes, K1-extreme init
// ============================================================
__global__ void params_kernel(const float* __restrict__ W1, const float* __restrict__ W2,
                              const float* __restrict__ b1, const float* __restrict__ b2,
                              const float* __restrict__ g1, const float* __restrict__ be1,
                              const float* __restrict__ m1, const float* __restrict__ var1,
                              const float* __restrict__ g2, const float* __restrict__ be2,
                              const float* __restrict__ m2, const float* __restrict__ var2) {
    int tid = threadIdx.x;
    if (tid < DD) {
        float A1 = g1[tid] * rsqrtf(var1[tid] + EPSV);
        g_A1f[tid] = A1; g_C1f[tid] = be1[tid] - A1 * m1[tid];
        float A2 = g2[tid] * rsqrtf(var2[tid] + EPSV);
        g_A2f[tid] = A2; g_C2f[tid] = be2[tid] - A2 * m2[tid];
        g_b12[tid] = b1[tid] + b2[tid];
    }
    for (int t = tid; t < BB*DD; t += blockDim.x) {
        g_K1mxE[t] = 0u;
        g_K1mnE[t] = 0xffffffffu;
    }
    for (int t = tid; t < 2*DIMQ*DD; t += blockDim.x) {
        int r = t / DD, d = t % DD;
        g_WqT[t] = (r < DIMQ) ? W1[d*256 + r*2] : W1[d*256 + (r - DIMQ)*2 + 1];
    }
    for (int t = tid; t < DIMQ*DD; t += blockDim.x) {
        int r = t / DD, d = t % DD;
        g_WkT[t] = W1[d*256 + 128 + r*2] + W1[d*256 + 128 + r*2 + 1];
    }
    if (tid < NPAD) {
        int d = tid;
        float mx = 0.f;
        if (d < DD)
            for (int k = 0; k < KK; k++) mx = fmaxf(mx, fabsf(W2[d*KK + k]));
        float u = mx / 127.f;
        g_Ud[d] = u;
        float inv = (mx > 0.f) ? 127.f / mx : 0.f;
        for (int w = 0; w < KW; w++) {
            uint32_t pk = 0;
            #pragma unroll
            for (int bpos = 0; bpos < 4; bpos++) {
                int k = 4*w + bpos;
                int q = 0;
                if (d < DD && k < KK) {
                    q = __float2int_rn(W2[d*KK + k] * inv);
                    q = max(-127, min(127, q));
                }
                pk |= ((uint32_t)(q & 0xff)) << (8*bpos);
            }
            g_Bq[d*KW + w] = pk;
        }
    }
}

// ============================================================
// Kernel 1: Q1[b][i][d], K1T[b][c][j] via transposed weights (coalesced on d)
// ============================================================
__global__ void prep_kernel(const float* __restrict__ q, const float* __restrict__ k) {
    int b = blockIdx.y;
    int task = blockIdx.x * blockDim.x + threadIdx.x;
    if (blockIdx.z == 0) {
        if (task >= SA*DD) return;
        int i = task / DD, d = task % DD;
        const float* q0 = q + (b*SS + i)*DIMQ;
        float s = 0.f;
        #pragma unroll 8
        for (int t = 0; t < DIMQ; t++)
            s += q0[t]*g_WqT[t*DD + d] + q0[DIMQ + t]*g_WqT[(DIMQ + t)*DD + d];
        g_Q1[(b*SS + i)*DD + d] = s;
    } else {
        if (task >= SS*DD) return;
        int j = task / DD, d = task % DD;
        const float* k0 = k + (b*SS + j)*DIMQ;
        float s = 0.f;
        #pragma unroll 8
        for (int t = 0; t < DIMQ; t++)
            s += k0[t]*g_WkT[t*DD + d];
        g_K1T[(b*DD + d)*SS + j] = s;
        unsigned e = fenc(s);
        atomicMax(&g_K1mxE[b*DD + d], e);
        atomicMin(&g_K1mnE[b*DD + d], e);
    }
}

// ============================================================
// Kernel 2: int8 mma.sync GEMM (m16n8k32 u8.s8.s32) + fused epilogue. occ=3.
// ============================================================
#define W_AQ   0
#define W_BQ   7680
#define W_PAR  13920
#define W_RED  (W_PAR + 10*NPAD)
#define SM_WORDS (W_RED + 516)

__global__ __launch_bounds__(256, 3)
void gemm2_mma(const float* __restrict__ b1, const float* __restrict__ W3) {
    extern __shared__ float sm[];
    uint32_t* Aq = (uint32_t*)sm + W_AQ;
    uint32_t* Bs = (uint32_t*)sm + W_BQ;
    float* Eb0 = sm + W_PAR;
    float* Eb1 = Eb0 + NPAD;
    float* A1s = Eb0 + 2*NPAD;
    float* A1z = Eb0 + 3*NPAD;
    float* Fb  = Eb0 + 4*NPAD;
    float* A2s = Eb0 + 5*NPAD;
    float* C2s = Eb0 + 6*NPAD;
    float* W30 = Eb0 + 7*NPAD;
    float* W31 = Eb0 + 8*NPAD;
    float* SUd = Eb0 + 9*NPAD;
    float* red0 = sm + W_RED;
    float* red1 = red0 + 256;
    int*   smaxi = (int*)(red0 + 512);

    int tid = threadIdx.x, wid = tid >> 5, lane = tid & 31;
    int j0 = blockIdx.x * 128, i = blockIdx.y, b = blockIdx.z;

    if (tid == 0) *smaxi = 0;

    {
        const uint4* src = (const uint4*)g_Bq;
        for (int t = tid; t < NPAD*(KW/4); t += 256) {
            int d = t / (KW/4), w4 = t % (KW/4);
            *(uint4*)(Bs + d*RSTR + 4*w4) = src[t];
        }
    }
    if (tid < NPAD) SUd[tid] = g_Ud[tid];
    if (tid < DD) {
        float A1 = g_A1f[tid], C1 = g_C1f[tid];
        float bb = b1[tid];
        float e1 = fmaf(A1, g_Q1[(b*SS + i)*DD + tid] + bb, C1);
        float e0 = (i > 0) ? fmaf(A1, g_Q1[(b*SS + i - 1)*DD + tid] + bb, C1) : C1;
        float a1z = (i > 0) ? A1 : 0.f;
        Eb1[tid] = e1; Eb0[tid] = e0;
        A1s[tid] = A1; A1z[tid] = a1z;
        Fb[tid]  = g_b12[tid] + g_Q1[(b*SS + i)*DD + tid];
        A2s[tid] = g_A2f[tid];
        C2s[tid] = g_C2f[tid];
        W30[tid] = W3[2*tid];
        W31[tid] = W3[2*tid + 1];
        float kx = fdec(g_K1mxE[b*DD + tid]);
        float kn = fdec(g_K1mnE[b*DD + tid]);
        float m = fmaxf(fmaxf(fmaxf(fmaf(a1z, kx, e0), fmaf(a1z, kn, e0)),
                              fmaxf(fmaf(A1,  kx, e1), fmaf(A1,  kn, e1))), 0.f);
        atomicMax(smaxi, __float_as_int(m));
    }
    __syncthreads();

    float amax = __int_as_float(*smaxi);
    float s_a   = amax / 255.f;
    float inv_s = (amax > 0.f) ? 255.f / amax : 0.f;

    {
        int j = tid & 127, half = tid >> 7;
        const float* kcol = g_K1T + (size_t)b*DD*SS + j0 + j;
        uint32_t* arow = Aq + j*RSTR;
        #pragma unroll 5
        for (int w = half*25; w < half*25 + 25; w++) {
            int c0 = 2*w, c1 = 2*w + 1;
            float kv0 = kcol[(size_t)c0*SS];
            float kv1 = kcol[(size_t)c1*SS];
            float v00 = fmaxf(fmaf(A1z[c0], kv0, Eb0[c0]), 0.f);
            float v01 = fmaxf(fmaf(A1s[c0], kv0, Eb1[c0]), 0.f);
            float v10 = fmaxf(fmaf(A1z[c1], kv1, Eb0[c1]), 0.f);
            float v11 = fmaxf(fmaf(A1s[c1], kv1, Eb1[c1]), 0.f);
            uint32_t q0 = min(__float2uint_rn(v00 * inv_s), 255u);
            uint32_t q1 = min(__float2uint_rn(v01 * inv_s), 255u);
            uint32_t q2 = min(__float2uint_rn(v10 * inv_s), 255u);
            uint32_t q3 = min(__float2uint_rn(v11 * inv_s), 255u);
            arow[w] = q0 | (q1 << 8) | (q2 << 16) | (q3 << 24);
        }
        arow[50 + half*3]     = 0u;
        arow[50 + half*3 + 1] = 0u;
        arow[50 + half*3 + 2] = 0u;
    }
    __syncthreads();

    int C[NT][4];
    #pragma unroll
    for (int nt = 0; nt < NT; nt++)
        #pragma unroll
        for (int r = 0; r < 4; r++) C[nt][r] = 0;

    {
        int ly = lane >> 2, lx = lane & 3;
        int jw = wid * 16;
        const uint32_t* arow0 = Aq + (jw + ly)*RSTR;
        const uint32_t* arow1 = Aq + (jw + ly + 8)*RSTR;
        const uint32_t* brow  = Bs + ly*RSTR;
        #pragma unroll
        for (int ks = 0; ks < KS32; ks++) {
            int kw = 8*ks;
            uint32_t a0 = arow0[kw + lx];
            uint32_t a1 = arow1[kw + lx];
            uint32_t a2 = arow0[kw + lx + 4];
            uint32_t a3 = arow1[kw + lx + 4];
            #pragma unroll
            for (int nt = 0; nt < NT; nt++) {
                uint32_t b0 = brow[nt*8*RSTR + kw + lx];
                uint32_t b1v = brow[nt*8*RSTR + kw + lx + 4];
                mma_u8s8(C[nt], a0, a1, a2, a3, b0, b1v);
            }
        }
    }
    __syncthreads();

    float* Cs = sm;
    {
        int ly = lane >> 2, lx = lane & 3;
        int jw = wid * 16;
        #pragma unroll
        for (int nt = 0; nt < NT; nt++) {
            int col = 8*nt + 2*lx;
            float u0 = s_a * SUd[col], u1 = s_a * SUd[col + 1];
            *(float2*)(Cs + (jw + ly    )*CSTR + col) =
                make_float2((float)C[nt][0] * u0, (float)C[nt][1] * u1);
            *(float2*)(Cs + (jw + ly + 8)*CSTR + col) =
                make_float2((float)C[nt][2] * u0, (float)C[nt][3] * u1);
        }
    }
    __syncthreads();

    {
        int jrow = tid & 127, dhalf = tid >> 7;
        const float* kcol = g_K1T + (size_t)b*DD*SS + j0 + jrow;
        float p0 = 0.f, p1 = 0.f;
        #pragma unroll 5
        for (int d = dhalf*50; d < dhalf*50 + 50; d++) {
            float t = Cs[jrow*CSTR + d] + Fb[d] + kcol[(size_t)d*SS];
            float val = fmaxf(fmaf(A2s[d], t, C2s[d]), 0.f);
            p0 = fmaf(W30[d], val, p0);
            p1 = fmaf(W31[d], val, p1);
        }
        red0[tid] = p0; red1[tid] = p1;
        __syncthreads();
        if (tid < 128) {
            g_P0[(size_t)(b*SS + i)*SS + j0 + tid] = red0[tid] + red0[tid + 128];
        } else {
            int j = tid - 128;
            g_P1[(size_t)(b*SS + i)*SS + j0 + j] = red1[j] + red1[j + 128];
        }
    }
}

// ============================================================
// Kernel 3: 4 rows per block; v staged in smem; float4 AV.
// grid (64, BB), 256 threads. smem ~82KB -> occ 2.
// Output: [ out (8*254*64) | attn (8*254*256) ]
// ============================================================
#define GR    4
#define VSTR  68                        // float stride per v row (16 float4 + pad)
#define AW_VS 0                         // v:    256*VSTR = 17408 floats
#define AW_AT (256*VSTR)                // attn: GR*256 = 1024
#define AW_RV (AW_AT + GR*256)          // redv: 8*GR*16*4 = 2048
#define AW_PM (AW_RV + 2048)            // pm[8], ps[8], sinv[GR]
#define AT_WORDS (AW_PM + 8 + 8 + GR)

__global__ __launch_bounds__(256, 2)
void attn_kernel(const float* __restrict__ b3, const float* __restrict__ v,
                 float* __restrict__ out) {
    extern __shared__ float smA[];
    float* vs   = smA + AW_VS;
    float* attn = smA + AW_AT;          // unnormalized exp values, [r][j]
    float* redv = smA + AW_RV;          // [g8][r][t4] float4
    float* pm   = smA + AW_PM;
    float* ps   = pm + 8;
    float* sinv = ps + 8;

    int tid = threadIdx.x, w = tid >> 5, lane = tid & 31;
    int i0 = blockIdx.x * GR, b = blockIdx.y;

    // ---- stage v[b] (64KB) into smem, float4 coalesced ----
    for (int idx = tid; idx < 256*16; idx += 256) {
        int j = idx >> 4, t4 = idx & 15;
        *(float4*)(vs + j*VSTR + t4*4) =
            *(const float4*)(v + ((size_t)(b*SS) + j)*DIMQ + t4*4);
    }

    // ---- logits + softmax: warp pair (r, r+4) covers row r's 256 j ----
    int r = w & 3, half = w >> 2;
    int i = min(i0 + r, SO - 1);        // clamp (guarded at store)
    int j4 = half*128 + lane*4;
    float4 p0 = *(const float4*)(g_P0 + ((size_t)(b*SS + i))*SS + j4);
    float4 p1 = *(const float4*)(g_P1 + ((size_t)(b*SS + i + 1))*SS + j4);
    float bias = b3[0];
    float4 lg;
    lg.x = (bias + p0.x + p1.x) * TEMP_INV;
    lg.y = (bias + p0.y + p1.y) * TEMP_INV;
    lg.z = (bias + p0.z + p1.z) * TEMP_INV;
    lg.w = (bias + p0.w + p1.w) * TEMP_INV;

    float m = fmaxf(fmaxf(lg.x, lg.y), fmaxf(lg.z, lg.w));
    #pragma unroll
    for (int o = 16; o > 0; o >>= 1) m = fmaxf(m, __shfl_xor_sync(~0u, m, o));
    if (lane == 0) pm[w] = m;
    __syncthreads();
    float mx = fmaxf(pm[r], pm[r + 4]);

    float4 e;
    e.x = __expf(lg.x - mx); e.y = __expf(lg.y - mx);
    e.z = __expf(lg.z - mx); e.w = __expf(lg.w - mx);
    *(float4*)(attn + r*256 + j4) = e;
    float s = e.x + e.y + e.z + e.w;
    #pragma unroll
    for (int o = 16; o > 0; o >>= 1) s += __shfl_xor_sync(~0u, s, o);
    if (lane == 0) ps[w] = s;
    __syncthreads();
    if (tid < GR) sinv[tid] = 1.f / (ps[tid] + ps[tid + 4]);
    __syncthreads();

    // attn output (normalized)
    {
        int ii = i0 + r;
        if (ii < SO) {
            float inv = sinv[r];
            float4 a4 = make_float4(e.x*inv, e.y*inv, e.z*inv, e.w*inv);
            *(float4*)(out + (size_t)BB*SO*DIMQ + ((size_t)(b*SO + ii))*SS + j4) = a4;
        }
    }

    // ---- AV: warp g covers j in [g*32, g*32+32); lane = (jh, t4) ----
    {
        int t4 = lane & 15, jh = lane >> 4;
        int jb = w*32 + jh*16;
        float4 acc[GR];
        #pragma unroll
        for (int rr = 0; rr < GR; rr++) acc[rr] = make_float4(0.f, 0.f, 0.f, 0.f);
        #pragma unroll 4
        for (int jj = 0; jj < 16; jj++) {
            int j = jb + jj;
            float4 v4 = *(float4*)(vs + j*VSTR + t4*4);
            #pragma unroll
            for (int rr = 0; rr < GR; rr++) {
                float a = attn[rr*256 + j];
                acc[rr].x = fmaf(a, v4.x, acc[rr].x);
                acc[rr].y = fmaf(a, v4.y, acc[rr].y);
                acc[rr].z = fmaf(a, v4.z, acc[rr].z);
                acc[rr].w = fmaf(a, v4.w, acc[rr].w);
            }
        }
        // combine jh halves within warp
        #pragma unroll
        for (int rr = 0; rr < GR; rr++) {
            acc[rr].x += __shfl_xor_sync(~0u, acc[rr].x, 16);
            acc[rr].y += __shfl_xor_sync(~0u, acc[rr].y, 16);
            acc[rr].z += __shfl_xor_sync(~0u, acc[rr].z, 16);
            acc[rr].w += __shfl_xor_sync(~0u, acc[rr].w, 16);
        }
        if (jh == 0) {
            #pragma unroll
            for (int rr = 0; rr < GR; rr++)
                *(float4*)(redv + ((w*GR + rr)*16 + t4)*4) = acc[rr];
        }
    }
    __syncthreads();
    if (tid < 64) {
        int rr = tid >> 4, tt = tid & 15;
        float4 o = make_float4(0.f, 0.f, 0.f, 0.f);
        #pragma unroll
        for (int g = 0; g < 8; g++) {
            float4 x = *(float4*)(redv + ((g*GR + rr)*16 + tt)*4);
            o.x += x.x; o.y += x.y; o.z += x.z; o.w += x.w;
        }
        int ii = i0 + rr;
        if (ii < SO) {
            float inv = sinv[rr];
            o.x *= inv; o.y *= inv; o.z *= inv; o.w *= inv;
            *(float4*)(out + ((size_t)(b*SO + ii))*DIMQ + tt*4) = o;
        }
    }
}

// ============================================================
extern "C" void kernel_launch(void* const* d_in, const int* in_sizes, int n_in,
                              void* d_out, int out_size) {
    const float* q    = (const float*)d_in[0];
    const float* k    = (const float*)d_in[1];
    const float* v    = (const float*)d_in[2];
    const float* W1   = (const float*)d_in[3];
    const float* b1   = (const float*)d_in[4];
    const float* g1   = (const float*)d_in[5];
    const float* be1  = (const float*)d_in[6];
    const float* m1   = (const float*)d_in[7];
    const float* var1 = (const float*)d_in[8];
    const float* W2   = (const float*)d_in[9];
    const float* b2   = (const float*)d_in[10];
    const float* g2   = (const float*)d_in[11];
    const float* be2  = (const float*)d_in[12];
    const float* m2   = (const float*)d_in[13];
    const float* var2 = (const float*)d_in[14];
    const float* W3   = (const float*)d_in[15];
    const float* b3   = (const float*)d_in[16];
    float* out = (float*)d_out;

    cudaFuncSetAttribute(gemm2_mma, cudaFuncAttributeMaxDynamicSharedMemorySize,
                         SM_WORDS * (int)sizeof(float));
    cudaFuncSetAttribute(attn_kernel, cudaFuncAttributeMaxDynamicSharedMemorySize,
                         AT_WORDS * (int)sizeof(float));

    params_kernel<<<1, 256>>>(W1, W2, b1, b2, g1, be1, m1, var1, g2, be2, m2, var2);
    prep_kernel  <<<dim3((SS*DD + 255)/256, BB, 2), 256>>>(q, k);
    gemm2_mma    <<<dim3(2, SA, BB), 256, SM_WORDS*sizeof(float)>>>(b1, W3);
    attn_kernel  <<<dim3((SO + GR - 1)/GR, BB), 256, AT_WORDS*sizeof(float)>>>(b3, v, out);
}

// round 16
// speedup vs baseline: 1.0668x; 1.0668x over previous
#include <cuda_runtime.h>
#include <cuda_fp16.h>
#include <cstdint>

// Problem constants
#define BB    8
#define SS    256
#define DIMQ  64
#define DD    100
#define SA    255   // rows of a2
#define SO    254   // output rows
#define TEMP_INV 0.1f
#define EPSV  1e-5f

// GEMM tiling per (b, i, jtile): D[j=128, d=104] = A[j,k] * B[d,k], K padded 200->224 (int8 k32)
#define NPAD  104
#define KK    200
#define NT    13      // 104/8 n-tiles
#define KS32  7       // 224/32 k-steps
#define KW    56      // data words per row (224 bytes / 4)
#define RSTR  60      // smem row stride in u32 words; 60%32=28 -> conflict-free frag loads
#define CSTR  106     // even -> 8B-aligned float2 staging rows; fits under 13920 words

// Scratch (device globals: no allocation allowed)
__device__ float g_Q1[BB*SS*DD];            // [b][i][d]
__device__ float g_K1T[BB*DD*SS];           // [b][c][j]
__device__ float g_P0[BB*SS*SS];            // conv3 partial, h=0 tap
__device__ float g_P1[BB*SS*SS];            // conv3 partial, h=1 tap
__device__ uint32_t g_Bq[NPAD*KW];          // W2 quantized s8, packed words [d][k/4]
__device__ float g_Ud[NPAD];                // per-d B dequant scales
__device__ unsigned g_K1mxE[BB*DD];         // encoded per-(b,c) max of K1
__device__ unsigned g_K1mnE[BB*DD];         // encoded per-(b,c) min of K1
__device__ float g_WqT[2*DIMQ*DD];          // W1 q-branch transposed: [t2][d] (t2=0..127)
__device__ float g_WkT[DIMQ*DD];            // W1 k-branch taps summed, transposed: [t][d]
__device__ float g_A1f[DD], g_C1f[DD], g_A2f[DD], g_C2f[DD], g_b12[DD];

// ---------------- helpers ----------------
__device__ __forceinline__ unsigned fenc(float f) {
    unsigned u = __float_as_uint(f);
    return (u & 0x80000000u) ? ~u : (u | 0x80000000u);
}
__device__ __forceinline__ float fdec(unsigned u) {
    unsigned v = (u & 0x80000000u) ? (u & 0x7fffffffu) : ~u;
    return __uint_as_float(v);
}
__device__ __forceinline__ void mma_u8s8(int* c, uint32_t a0, uint32_t a1, uint32_t a2,
                                         uint32_t a3, uint32_t b0, uint32_t b1) {
    asm volatile(
        "mma.sync.aligned.m16n8k32.row.col.s32.u8.s8.s32 "
        "{%0,%1,%2,%3}, {%4,%5,%6,%7}, {%8,%9}, {%0,%1,%2,%3};"
        : "+r"(c[0]), "+r"(c[1]), "+r"(c[2]), "+r"(c[3])
        : "r"(a0), "r"(a1), "r"(a2), "r"(a3), "r"(b0), "r"(b1));
}

// ============================================================
// Kernel 0a: params — bn folds, W1 transposes, K1-extreme init
// ============================================================
__global__ void params_kernel(const float* __restrict__ W1,
                              const float* __restrict__ b1, const float* __restrict__ b2,
                              const float* __restrict__ g1, const float* __restrict__ be1,
                              const float* __restrict__ m1, const float* __restrict__ var1,
                              const float* __restrict__ g2, const float* __restrict__ be2,
                              const float* __restrict__ m2, const float* __restrict__ var2) {
    int tid = threadIdx.x;
    if (tid < DD) {
        float A1 = g1[tid] * rsqrtf(var1[tid] + EPSV);
        g_A1f[tid] = A1; g_C1f[tid] = be1[tid] - A1 * m1[tid];
        float A2 = g2[tid] * rsqrtf(var2[tid] + EPSV);
        g_A2f[tid] = A2; g_C2f[tid] = be2[tid] - A2 * m2[tid];
        g_b12[tid] = b1[tid] + b2[tid];
    }
    for (int t = tid; t < BB*DD; t += blockDim.x) {
        g_K1mxE[t] = 0u;
        g_K1mnE[t] = 0xffffffffu;
    }
    for (int t = tid; t < 2*DIMQ*DD; t += blockDim.x) {
        int r = t / DD, d = t % DD;
        g_WqT[t] = (r < DIMQ) ? W1[d*256 + r*2] : W1[d*256 + (r - DIMQ)*2 + 1];
    }
    for (int t = tid; t < DIMQ*DD; t += blockDim.x) {
        int r = t / DD, d = t % DD;
        g_WkT[t] = W1[d*256 + 128 + r*2] + W1[d*256 + 128 + r*2 + 1];
    }
}

// ============================================================
// Kernel 0b: per-d W2 int8 quantization. One block per d (104 blocks, 64 thr).
// ============================================================
__global__ void quantW2_kernel(const float* __restrict__ W2) {
    int d = blockIdx.x;              // 0..NPAD-1
    int tid = threadIdx.x;           // 64 threads
    __shared__ float wm[2];
    __shared__ float s_inv;

    float mx = 0.f;
    if (d < DD)
        for (int k = tid; k < KK; k += 64) mx = fmaxf(mx, fabsf(W2[d*KK + k]));
    #pragma unroll
    for (int o = 16; o > 0; o >>= 1) mx = fmaxf(mx, __shfl_xor_sync(~0u, mx, o));
    if ((tid & 31) == 0) wm[tid >> 5] = mx;
    __syncthreads();
    if (tid == 0) {
        float m = fmaxf(wm[0], wm[1]);
        g_Ud[d] = m / 127.f;
        s_inv = (m > 0.f) ? 127.f / m : 0.f;
    }
    __syncthreads();
    float inv = s_inv;
    for (int w = tid; w < KW; w += 64) {
        uint32_t pk = 0;
        #pragma unroll
        for (int bpos = 0; bpos < 4; bpos++) {
            int k = 4*w + bpos;
            int q = 0;
            if (d < DD && k < KK) {
                q = __float2int_rn(W2[d*KK + k] * inv);
                q = max(-127, min(127, q));
            }
            pk |= ((uint32_t)(q & 0xff)) << (8*bpos);
        }
        g_Bq[d*KW + w] = pk;
    }
}

// ============================================================
// Kernel 1: Q1[b][i][d], K1T[b][c][j] via transposed weights (coalesced on d)
// ============================================================
__global__ void prep_kernel(const float* __restrict__ q, const float* __restrict__ k) {
    int b = blockIdx.y;
    int task = blockIdx.x * blockDim.x + threadIdx.x;
    if (blockIdx.z == 0) {
        if (task >= SA*DD) return;
        int i = task / DD, d = task % DD;
        const float* q0 = q + (b*SS + i)*DIMQ;
        float s = 0.f;
        #pragma unroll 8
        for (int t = 0; t < DIMQ; t++)
            s += q0[t]*g_WqT[t*DD + d] + q0[DIMQ + t]*g_WqT[(DIMQ + t)*DD + d];
        g_Q1[(b*SS + i)*DD + d] = s;
    } else {
        if (task >= SS*DD) return;
        int j = task / DD, d = task % DD;
        const float* k0 = k + (b*SS + j)*DIMQ;
        float s = 0.f;
        #pragma unroll 8
        for (int t = 0; t < DIMQ; t++)
            s += k0[t]*g_WkT[t*DD + d];
        g_K1T[(b*DD + d)*SS + j] = s;
        unsigned e = fenc(s);
        atomicMax(&g_K1mxE[b*DD + d], e);
        atomicMin(&g_K1mnE[b*DD + d], e);
    }
}

// ============================================================
// Kernel 2: int8 mma.sync GEMM (m16n8k32 u8.s8.s32) + fused epilogue. occ=3.
// (unchanged — MAC-rate-capped at the fallback tensor path's ~220 MAC/cyc/SM)
// ============================================================
#define W_AQ   0
#define W_BQ   7680
#define W_PAR  13920
#define W_RED  (W_PAR + 10*NPAD)
#define SM_WORDS (W_RED + 516)

__global__ __launch_bounds__(256, 3)
void gemm2_mma(const float* __restrict__ b1, const float* __restrict__ W3) {
    extern __shared__ float sm[];
    uint32_t* Aq = (uint32_t*)sm + W_AQ;
    uint32_t* Bs = (uint32_t*)sm + W_BQ;
    float* Eb0 = sm + W_PAR;
    float* Eb1 = Eb0 + NPAD;
    float* A1s = Eb0 + 2*NPAD;
    float* A1z = Eb0 + 3*NPAD;
    float* Fb  = Eb0 + 4*NPAD;
    float* A2s = Eb0 + 5*NPAD;
    float* C2s = Eb0 + 6*NPAD;
    float* W30 = Eb0 + 7*NPAD;
    float* W31 = Eb0 + 8*NPAD;
    float* SUd = Eb0 + 9*NPAD;
    float* red0 = sm + W_RED;
    float* red1 = red0 + 256;
    int*   smaxi = (int*)(red0 + 512);

    int tid = threadIdx.x, wid = tid >> 5, lane = tid & 31;
    int j0 = blockIdx.x * 128, i = blockIdx.y, b = blockIdx.z;

    if (tid == 0) *smaxi = 0;

    {
        const uint4* src = (const uint4*)g_Bq;
        for (int t = tid; t < NPAD*(KW/4); t += 256) {
            int d = t / (KW/4), w4 = t % (KW/4);
            *(uint4*)(Bs + d*RSTR + 4*w4) = src[t];
        }
    }
    if (tid < NPAD) SUd[tid] = g_Ud[tid];
    if (tid < DD) {
        float A1 = g_A1f[tid], C1 = g_C1f[tid];
        float bb = b1[tid];
        float e1 = fmaf(A1, g_Q1[(b*SS + i)*DD + tid] + bb, C1);
        float e0 = (i > 0) ? fmaf(A1, g_Q1[(b*SS + i - 1)*DD + tid] + bb, C1) : C1;
        float a1z = (i > 0) ? A1 : 0.f;
        Eb1[tid] = e1; Eb0[tid] = e0;
        A1s[tid] = A1; A1z[tid] = a1z;
        Fb[tid]  = g_b12[tid] + g_Q1[(b*SS + i)*DD + tid];
        A2s[tid] = g_A2f[tid];
        C2s[tid] = g_C2f[tid];
        W30[tid] = W3[2*tid];
        W31[tid] = W3[2*tid + 1];
        float kx = fdec(g_K1mxE[b*DD + tid]);
        float kn = fdec(g_K1mnE[b*DD + tid]);
        float m = fmaxf(fmaxf(fmaxf(fmaf(a1z, kx, e0), fmaf(a1z, kn, e0)),
                              fmaxf(fmaf(A1,  kx, e1), fmaf(A1,  kn, e1))), 0.f);
        atomicMax(smaxi, __float_as_int(m));
    }
    __syncthreads();

    float amax = __int_as_float(*smaxi);
    float s_a   = amax / 255.f;
    float inv_s = (amax > 0.f) ? 255.f / amax : 0.f;

    {
        int j = tid & 127, half = tid >> 7;
        const float* kcol = g_K1T + (size_t)b*DD*SS + j0 + j;
        uint32_t* arow = Aq + j*RSTR;
        #pragma unroll 5
        for (int w = half*25; w < half*25 + 25; w++) {
            int c0 = 2*w, c1 = 2*w + 1;
            float kv0 = kcol[(size_t)c0*SS];
            float kv1 = kcol[(size_t)c1*SS];
            float v00 = fmaxf(fmaf(A1z[c0], kv0, Eb0[c0]), 0.f);
            float v01 = fmaxf(fmaf(A1s[c0], kv0, Eb1[c0]), 0.f);
            float v10 = fmaxf(fmaf(A1z[c1], kv1, Eb0[c1]), 0.f);
            float v11 = fmaxf(fmaf(A1s[c1], kv1, Eb1[c1]), 0.f);
            uint32_t q0 = min(__float2uint_rn(v00 * inv_s), 255u);
            uint32_t q1 = min(__float2uint_rn(v01 * inv_s), 255u);
            uint32_t q2 = min(__float2uint_rn(v10 * inv_s), 255u);
            uint32_t q3 = min(__float2uint_rn(v11 * inv_s), 255u);
            arow[w] = q0 | (q1 << 8) | (q2 << 16) | (q3 << 24);
        }
        arow[50 + half*3]     = 0u;
        arow[50 + half*3 + 1] = 0u;
        arow[50 + half*3 + 2] = 0u;
    }
    __syncthreads();

    int C[NT][4];
    #pragma unroll
    for (int nt = 0; nt < NT; nt++)
        #pragma unroll
        for (int r = 0; r < 4; r++) C[nt][r] = 0;

    {
        int ly = lane >> 2, lx = lane & 3;
        int jw = wid * 16;
        const uint32_t* arow0 = Aq + (jw + ly)*RSTR;
        const uint32_t* arow1 = Aq + (jw + ly + 8)*RSTR;
        const uint32_t* brow  = Bs + ly*RSTR;
        #pragma unroll
        for (int ks = 0; ks < KS32; ks++) {
            int kw = 8*ks;
            uint32_t a0 = arow0[kw + lx];
            uint32_t a1 = arow1[kw + lx];
            uint32_t a2 = arow0[kw + lx + 4];
            uint32_t a3 = arow1[kw + lx + 4];
            #pragma unroll
            for (int nt = 0; nt < NT; nt++) {
                uint32_t b0 = brow[nt*8*RSTR + kw + lx];
                uint32_t b1v = brow[nt*8*RSTR + kw + lx + 4];
                mma_u8s8(C[nt], a0, a1, a2, a3, b0, b1v);
            }
        }
    }
    __syncthreads();

    float* Cs = sm;
    {
        int ly = lane >> 2, lx = lane & 3;
        int jw = wid * 16;
        #pragma unroll
        for (int nt = 0; nt < NT; nt++) {
            int col = 8*nt + 2*lx;
            float u0 = s_a * SUd[col], u1 = s_a * SUd[col + 1];
            *(float2*)(Cs + (jw + ly    )*CSTR + col) =
                make_float2((float)C[nt][0] * u0, (float)C[nt][1] * u1);
            *(float2*)(Cs + (jw + ly + 8)*CSTR + col) =
                make_float2((float)C[nt][2] * u0, (float)C[nt][3] * u1);
        }
    }
    __syncthreads();

    {
        int jrow = tid & 127, dhalf = tid >> 7;
        const float* kcol = g_K1T + (size_t)b*DD*SS + j0 + jrow;
        float p0 = 0.f, p1 = 0.f;
        #pragma unroll 5
        for (int d = dhalf*50; d < dhalf*50 + 50; d++) {
            float t = Cs[jrow*CSTR + d] + Fb[d] + kcol[(size_t)d*SS];
            float val = fmaxf(fmaf(A2s[d], t, C2s[d]), 0.f);
            p0 = fmaf(W30[d], val, p0);
            p1 = fmaf(W31[d], val, p1);
        }
        red0[tid] = p0; red1[tid] = p1;
        __syncthreads();
        if (tid < 128) {
            g_P0[(size_t)(b*SS + i)*SS + j0 + tid] = red0[tid] + red0[tid + 128];
        } else {
            int j = tid - 128;
            g_P1[(size_t)(b*SS + i)*SS + j0 + j] = red1[j] + red1[j + 128];
        }
    }
}

// ============================================================
// Kernel 3: logits + softmax + AV. One block per (b, i) — R14 structure,
// AV vectorized: thread = (t4, grp); 16 float4 v-loads instead of 64 scalar.
// Output: [ out (8*254*64) | attn (8*254*256) ]
// ============================================================
__global__ void attn_kernel(const float* __restrict__ b3, const float* __restrict__ v,
                            float* __restrict__ out) {
    int i = blockIdx.x, b = blockIdx.y;
    int tid = threadIdx.x;   // = j
    int wid = tid >> 5, lane = tid & 31;
    __shared__ float wred[8];
    __shared__ float attn_s[256];
    __shared__ float red[1024];   // [grp 16][t 64]

    float logit = (b3[0] + g_P0[(size_t)(b*SS + i)*SS + tid]
                         + g_P1[(size_t)(b*SS + i + 1)*SS + tid]) * TEMP_INV;

    // warp max -> cross-warp max
    float m = logit;
    #pragma unroll
    for (int o = 16; o > 0; o >>= 1) m = fmaxf(m, __shfl_xor_sync(~0u, m, o));
    if (lane == 0) wred[wid] = m;
    __syncthreads();
    float mx = wred[0];
    #pragma unroll
    for (int w = 1; w < 8; w++) mx = fmaxf(mx, wred[w]);

    float p = __expf(logit - mx);
    float s = p;
    #pragma unroll
    for (int o = 16; o > 0; o >>= 1) s += __shfl_xor_sync(~0u, s, o);
    __syncthreads();              // wred reuse
    if (lane == 0) wred[wid] = s;
    __syncthreads();
    float tot = wred[0];
    #pragma unroll
    for (int w = 1; w < 8; w++) tot += wred[w];
    float inv = 1.f / tot;

    float a = p * inv;
    attn_s[tid] = a;
    out[(size_t)BB*SO*DIMQ + (size_t)(b*SO + i)*SS + tid] = a;
    __syncthreads();

    // AV: grp handles 16 j's; t4 covers 4 t's via float4 (v is L2-resident)
    int t4 = tid & 15, grp = tid >> 4;
    const float* vb = v + (size_t)b*SS*DIMQ;
    float4 acc = make_float4(0.f, 0.f, 0.f, 0.f);
    #pragma unroll 4
    for (int jj = 0; jj < 16; jj++) {
        int j = grp*16 + jj;
        float aw = attn_s[j];
        float4 v4 = *(const float4*)(vb + (size_t)j*DIMQ + t4*4);
        acc.x = fmaf(aw, v4.x, acc.x);
        acc.y = fmaf(aw, v4.y, acc.y);
        acc.z = fmaf(aw, v4.z, acc.z);
        acc.w = fmaf(aw, v4.w, acc.w);
    }
    *(float4*)(red + grp*64 + t4*4) = acc;
    __syncthreads();
    if (tid < 64) {
        float o = 0.f;
        #pragma unroll
        for (int g = 0; g < 16; g++) o += red[g*64 + tid];
        out[(size_t)(b*SO + i)*DIMQ + tid] = o;
    }
}

// ============================================================
extern "C" void kernel_launch(void* const* d_in, const int* in_sizes, int n_in,
                              void* d_out, int out_size) {
    const float* q    = (const float*)d_in[0];
    const float* k    = (const float*)d_in[1];
    const float* v    = (const float*)d_in[2];
    const float* W1   = (const float*)d_in[3];
    const float* b1   = (const float*)d_in[4];
    const float* g1   = (const float*)d_in[5];
    const float* be1  = (const float*)d_in[6];
    const float* m1   = (const float*)d_in[7];
    const float* var1 = (const float*)d_in[8];
    const float* W2   = (const float*)d_in[9];
    const float* b2   = (const float*)d_in[10];
    const float* g2   = (const float*)d_in[11];
    const float* be2  = (const float*)d_in[12];
    const float* m2   = (const float*)d_in[13];
    const float* var2 = (const float*)d_in[14];
    const float* W3   = (const float*)d_in[15];
    const float* b3   = (const float*)d_in[16];
    float* out = (float*)d_out;

    cudaFuncSetAttribute(gemm2_mma, cudaFuncAttributeMaxDynamicSharedMemorySize,
                         SM_WORDS * (int)sizeof(float));

    params_kernel<<<1, 256>>>(W1, b1, b2, g1, be1, m1, var1, g2, be2, m2, var2);
    quantW2_kernel<<<NPAD, 64>>>(W2);
    prep_kernel  <<<dim3((SS*DD + 255)/256, BB, 2), 256>>>(q, k);
    gemm2_mma    <<<dim3(2, SA, BB), 256, SM_WORDS*sizeof(float)>>>(b1, W3);
    attn_kernel  <<<dim3(SO, BB), 256>>>(b3, v, out);
}

// round 17
// speedup vs baseline: 1.1110x; 1.0414x over previous
#include <cuda_runtime.h>
#include <cuda_fp16.h>
#include <cstdint>

// Problem constants
#define BB    8
#define SS    256
#define DIMQ  64
#define DD    100
#define SA    255   // rows of a2
#define SO    254   // output rows
#define TEMP_INV 0.1f
#define EPSV  1e-5f

// GEMM tiling per (b, i, jtile): D[j=128, d=104] = A[j,k] * B[d,k], K padded 200->224 (int8 k32)
#define NPAD  104
#define KK    200
#define NT    13      // 104/8 n-tiles
#define KS32  7       // 224/32 k-steps
#define KW    56      // data words per row (224 bytes / 4)
#define RSTR  60      // A smem row stride (u32); 60%32=28 -> conflict-free frag loads
#define BSTR  56      // B stride == KW (contiguous copy); 2-way frag conflict accepted

// Scratch (device globals: no allocation allowed)
__device__ float g_Q1[BB*SS*DD];            // [b][i][d]
__device__ float g_K1T[BB*DD*SS];           // [b][c][j]
__device__ float g_P0[BB*SS*SS];            // conv3 partial, h=0 tap
__device__ float g_P1[BB*SS*SS];            // conv3 partial, h=1 tap
__device__ uint32_t g_Bq[NPAD*KW];          // W2 quantized s8, packed words [d][k/4]
__device__ float g_Ud[NPAD];                // per-d B dequant scales
__device__ unsigned g_K1mxE[BB*DD];         // encoded per-(b,c) max of K1
__device__ unsigned g_K1mnE[BB*DD];         // encoded per-(b,c) min of K1
__device__ float g_WqT[2*DIMQ*DD];          // W1 q-branch transposed: [t2][d]
__device__ float g_WkT[DIMQ*DD];            // W1 k-branch taps summed, transposed: [t][d]
__device__ float g_A1f[DD], g_C1f[DD], g_A2f[DD], g_C2f[DD], g_b12[DD];

// ---------------- helpers ----------------
__device__ __forceinline__ unsigned fenc(float f) {
    unsigned u = __float_as_uint(f);
    return (u & 0x80000000u) ? ~u : (u | 0x80000000u);
}
__device__ __forceinline__ float fdec(unsigned u) {
    unsigned v = (u & 0x80000000u) ? (u & 0x7fffffffu) : ~u;
    return __uint_as_float(v);
}
__device__ __forceinline__ void mma_u8s8(int* c, uint32_t a0, uint32_t a1, uint32_t a2,
                                         uint32_t a3, uint32_t b0, uint32_t b1) {
    asm volatile(
        "mma.sync.aligned.m16n8k32.row.col.s32.u8.s8.s32 "
        "{%0,%1,%2,%3}, {%4,%5,%6,%7}, {%8,%9}, {%0,%1,%2,%3};"
        : "+r"(c[0]), "+r"(c[1]), "+r"(c[2]), "+r"(c[3])
        : "r"(a0), "r"(a1), "r"(a2), "r"(a3), "r"(b0), "r"(b1));
}

// ============================================================
// Kernel 0a: params — bn folds, W1 transposes, K1-extreme init
// ============================================================
__global__ void params_kernel(const float* __restrict__ W1,
                              const float* __restrict__ b1, const float* __restrict__ b2,
                              const float* __restrict__ g1, const float* __restrict__ be1,
                              const float* __restrict__ m1, const float* __restrict__ var1,
                              const float* __restrict__ g2, const float* __restrict__ be2,
                              const float* __restrict__ m2, const float* __restrict__ var2) {
    int tid = threadIdx.x;
    if (tid < DD) {
        float A1 = g1[tid] * rsqrtf(var1[tid] + EPSV);
        g_A1f[tid] = A1; g_C1f[tid] = be1[tid] - A1 * m1[tid];
        float A2 = g2[tid] * rsqrtf(var2[tid] + EPSV);
        g_A2f[tid] = A2; g_C2f[tid] = be2[tid] - A2 * m2[tid];
        g_b12[tid] = b1[tid] + b2[tid];
    }
    for (int t = tid; t < BB*DD; t += blockDim.x) {
        g_K1mxE[t] = 0u;
        g_K1mnE[t] = 0xffffffffu;
    }
    for (int t = tid; t < 2*DIMQ*DD; t += blockDim.x) {
        int r = t / DD, d = t % DD;
        g_WqT[t] = (r < DIMQ) ? W1[d*256 + r*2] : W1[d*256 + (r - DIMQ)*2 + 1];
    }
    for (int t = tid; t < DIMQ*DD; t += blockDim.x) {
        int r = t / DD, d = t % DD;
        g_WkT[t] = W1[d*256 + 128 + r*2] + W1[d*256 + 128 + r*2 + 1];
    }
}

// ============================================================
// Kernel 0b: per-d W2 int8 quantization. One block per d.
// ============================================================
__global__ void quantW2_kernel(const float* __restrict__ W2) {
    int d = blockIdx.x;
    int tid = threadIdx.x;           // 64 threads
    __shared__ float wm[2];
    __shared__ float s_inv;

    float mx = 0.f;
    if (d < DD)
        for (int k = tid; k < KK; k += 64) mx = fmaxf(mx, fabsf(W2[d*KK + k]));
    #pragma unroll
    for (int o = 16; o > 0; o >>= 1) mx = fmaxf(mx, __shfl_xor_sync(~0u, mx, o));
    if ((tid & 31) == 0) wm[tid >> 5] = mx;
    __syncthreads();
    if (tid == 0) {
        float m = fmaxf(wm[0], wm[1]);
        g_Ud[d] = m / 127.f;
        s_inv = (m > 0.f) ? 127.f / m : 0.f;
    }
    __syncthreads();
    float inv = s_inv;
    for (int w = tid; w < KW; w += 64) {
        uint32_t pk = 0;
        #pragma unroll
        for (int bpos = 0; bpos < 4; bpos++) {
            int k = 4*w + bpos;
            int q = 0;
            if (d < DD && k < KK) {
                q = __float2int_rn(W2[d*KK + k] * inv);
                q = max(-127, min(127, q));
            }
            pk |= ((uint32_t)(q & 0xff)) << (8*bpos);
        }
        g_Bq[d*KW + w] = pk;
    }
}

// ============================================================
// Kernel 1: Q1[b][i][d], K1T[b][c][j] via transposed weights
// ============================================================
__global__ void prep_kernel(const float* __restrict__ q, const float* __restrict__ k) {
    int b = blockIdx.y;
    int task = blockIdx.x * blockDim.x + threadIdx.x;
    if (blockIdx.z == 0) {
        if (task >= SA*DD) return;
        int i = task / DD, d = task % DD;
        const float* q0 = q + (b*SS + i)*DIMQ;
        float s = 0.f;
        #pragma unroll 8
        for (int t = 0; t < DIMQ; t++)
            s += q0[t]*g_WqT[t*DD + d] + q0[DIMQ + t]*g_WqT[(DIMQ + t)*DD + d];
        g_Q1[(b*SS + i)*DD + d] = s;
    } else {
        if (task >= SS*DD) return;
        int j = task / DD, d = task % DD;
        const float* k0 = k + (b*SS + j)*DIMQ;
        float s = 0.f;
        #pragma unroll 8
        for (int t = 0; t < DIMQ; t++)
            s += k0[t]*g_WkT[t*DD + d];
        g_K1T[(b*DD + d)*SS + j] = s;
        unsigned e = fenc(s);
        atomicMax(&g_K1mxE[b*DD + d], e);
        atomicMin(&g_K1mnE[b*DD + d], e);
    }
}

// ============================================================
// Kernel 2: int8 mma.sync GEMM + register-direct fused epilogue. occ=4.
//  - no C staging: bn2/relu/conv3 partials computed from mma fragments,
//    reduced over lx lanes with shfl.
//  - phase-split params: A-gen params and epilogue params share one
//    624-word union region (loaded before / after the mainloop).
//  smem = 7680(A) + 5824(B) + 624(union) + 4 = 14132 words = 56528 B -> 4 CTAs/SM
// ============================================================
#define W_AQ   0
#define W_BQ   7680
#define W_UN   (W_BQ + NPAD*BSTR)     // 13504
#define W_SC   (W_UN + 624)           // 14128
#define SM_WORDS (W_SC + 4)           // 14132 words = 56528 B

__global__ __launch_bounds__(256, 4)
void gemm2_mma(const float* __restrict__ b1, const float* __restrict__ W3) {
    extern __shared__ float sm[];
    uint32_t* Aq = (uint32_t*)sm + W_AQ;
    uint32_t* Bs = (uint32_t*)sm + W_BQ;
    float* UN = sm + W_UN;
    // phase A (pre-mainloop): Eb0, Eb1, A1s, A1z
    float* Eb0 = UN;         float* Eb1 = UN + 104;
    float* A1s = UN + 208;   float* A1z = UN + 312;
    // phase B (post-mainloop): Fb, A2s, C2s, W30, W31, SUd (overwrites phase A)
    float* Fb  = UN;         float* A2s = UN + 104;  float* C2s = UN + 208;
    float* W30 = UN + 312;   float* W31 = UN + 416;  float* SUd = UN + 520;
    int* smaxi = (int*)(sm + W_SC);

    int tid = threadIdx.x, wid = tid >> 5, lane = tid & 31;
    int j0 = blockIdx.x * 128, i = blockIdx.y, b = blockIdx.z;

    if (tid == 0) *smaxi = 0;

    // ---- B: contiguous copy of pre-quantized s8 image (BSTR == KW) ----
    {
        const uint4* src = (const uint4*)g_Bq;
        uint4* dst = (uint4*)Bs;
        for (int t = tid; t < NPAD*KW/4; t += 256) dst[t] = src[t];
    }
    // ---- phase A params + analytic tile-max ----
    if (tid < DD) {
        float A1 = g_A1f[tid], C1 = g_C1f[tid];
        float bb = b1[tid];
        float e1 = fmaf(A1, g_Q1[(b*SS + i)*DD + tid] + bb, C1);
        float e0 = (i > 0) ? fmaf(A1, g_Q1[(b*SS + i - 1)*DD + tid] + bb, C1) : C1;
        float a1z = (i > 0) ? A1 : 0.f;
        Eb1[tid] = e1; Eb0[tid] = e0;
        A1s[tid] = A1; A1z[tid] = a1z;
        float kx = fdec(g_K1mxE[b*DD + tid]);
        float kn = fdec(g_K1mnE[b*DD + tid]);
        float m = fmaxf(fmaxf(fmaxf(fmaf(a1z, kx, e0), fmaf(a1z, kn, e0)),
                              fmaxf(fmaf(A1,  kx, e1), fmaf(A1,  kn, e1))), 0.f);
        atomicMax(smaxi, __float_as_int(m));
    }
    __syncthreads();

    float amax = __int_as_float(*smaxi);
    float s_a   = amax / 255.f;
    float inv_s = (amax > 0.f) ? 255.f / amax : 0.f;

    // ---- A generation: r1 on the fly -> u8 quantize -> packed words ----
    {
        int j = tid & 127, half = tid >> 7;
        const float* kcol = g_K1T + (size_t)b*DD*SS + j0 + j;
        uint32_t* arow = Aq + j*RSTR;
        #pragma unroll 5
        for (int w = half*25; w < half*25 + 25; w++) {
            int c0 = 2*w, c1 = 2*w + 1;
            float kv0 = kcol[(size_t)c0*SS];
            float kv1 = kcol[(size_t)c1*SS];
            float v00 = fmaxf(fmaf(A1z[c0], kv0, Eb0[c0]), 0.f);
            float v01 = fmaxf(fmaf(A1s[c0], kv0, Eb1[c0]), 0.f);
            float v10 = fmaxf(fmaf(A1z[c1], kv1, Eb0[c1]), 0.f);
            float v11 = fmaxf(fmaf(A1s[c1], kv1, Eb1[c1]), 0.f);
            uint32_t q0 = min(__float2uint_rn(v00 * inv_s), 255u);
            uint32_t q1 = min(__float2uint_rn(v01 * inv_s), 255u);
            uint32_t q2 = min(__float2uint_rn(v10 * inv_s), 255u);
            uint32_t q3 = min(__float2uint_rn(v11 * inv_s), 255u);
            arow[w] = q0 | (q1 << 8) | (q2 << 16) | (q3 << 24);
        }
        arow[50 + half*3]     = 0u;
        arow[50 + half*3 + 1] = 0u;
        arow[50 + half*3 + 2] = 0u;
    }
    __syncthreads();

    // ---- MMA mainloop: warp tile 16j x 104d, m16n8k32 u8.s8 ----
    int C[NT][4];
    #pragma unroll
    for (int nt = 0; nt < NT; nt++)
        #pragma unroll
        for (int r = 0; r < 4; r++) C[nt][r] = 0;

    int ly = lane >> 2, lx = lane & 3;
    int jw = wid * 16;
    {
        const uint32_t* arow0 = Aq + (jw + ly)*RSTR;
        const uint32_t* arow1 = Aq + (jw + ly + 8)*RSTR;
        const uint32_t* brow  = Bs + ly*BSTR;
        #pragma unroll
        for (int ks = 0; ks < KS32; ks++) {
            int kw = 8*ks;
            uint32_t a0 = arow0[kw + lx];
            uint32_t a1 = arow1[kw + lx];
            uint32_t a2 = arow0[kw + lx + 4];
            uint32_t a3 = arow1[kw + lx + 4];
            #pragma unroll
            for (int nt = 0; nt < NT; nt++) {
                uint32_t b0 = brow[nt*8*BSTR + kw + lx];
                uint32_t b1v = brow[nt*8*BSTR + kw + lx + 4];
                mma_u8s8(C[nt], a0, a1, a2, a3, b0, b1v);
            }
        }
    }
    __syncthreads();   // mainloop done everywhere before union region is overwritten

    // ---- phase B params ----
    for (int t = tid; t < NPAD; t += 256) {
        bool ok = (t < DD);
        Fb[t]  = ok ? (g_b12[t] + g_Q1[(b*SS + i)*DD + t]) : 0.f;
        A2s[t] = ok ? g_A2f[t] : 0.f;
        C2s[t] = ok ? g_C2f[t] : 0.f;
        W30[t] = ok ? W3[2*t] : 0.f;
        W31[t] = ok ? W3[2*t + 1] : 0.f;
        SUd[t] = g_Ud[t];
    }
    __syncthreads();

    // ---- register-direct epilogue: dequant + residual + bn2 + relu + conv3 ----
    {
        int jA = j0 + jw + ly, jB = jA + 8;
        const float* k1b = g_K1T + (size_t)b*DD*SS;
        float p0A = 0.f, p1A = 0.f, p0B = 0.f, p1B = 0.f;
        #pragma unroll
        for (int nt = 0; nt < NT; nt++) {
            int d0 = 8*nt + 2*lx, d1 = d0 + 1;
            int dc0 = min(d0, DD-1), dc1 = min(d1, DD-1);  // clamp pad-d loads
            float k0A = k1b[(size_t)dc0*SS + jA];
            float k1A = k1b[(size_t)dc1*SS + jA];
            float k0B = k1b[(size_t)dc0*SS + jB];
            float k1B = k1b[(size_t)dc1*SS + jB];
            float u0 = s_a * SUd[d0], u1 = s_a * SUd[d1];
            float a20 = A2s[d0], a21 = A2s[d1];
            float c20 = C2s[d0], c21 = C2s[d1];
            float f0 = Fb[d0], f1 = Fb[d1];
            float w00 = W30[d0], w01 = W30[d1];
            float w10 = W31[d0], w11 = W31[d1];

            float vA0 = fmaxf(fmaf(a20, (float)C[nt][0]*u0 + f0 + k0A, c20), 0.f);
            float vA1 = fmaxf(fmaf(a21, (float)C[nt][1]*u1 + f1 + k1A, c21), 0.f);
            float vB0 = fmaxf(fmaf(a20, (float)C[nt][2]*u0 + f0 + k0B, c20), 0.f);
            float vB1 = fmaxf(fmaf(a21, (float)C[nt][3]*u1 + f1 + k1B, c21), 0.f);

            p0A = fmaf(w00, vA0, p0A); p0A = fmaf(w01, vA1, p0A);
            p1A = fmaf(w10, vA0, p1A); p1A = fmaf(w11, vA1, p1A);
            p0B = fmaf(w00, vB0, p0B); p0B = fmaf(w01, vB1, p0B);
            p1B = fmaf(w10, vB0, p1B); p1B = fmaf(w11, vB1, p1B);
        }
        // reduce over lx (lanes differ in bits 0-1)
        #pragma unroll
        for (int o = 1; o < 4; o <<= 1) {
            p0A += __shfl_xor_sync(~0u, p0A, o);
            p1A += __shfl_xor_sync(~0u, p1A, o);
            p0B += __shfl_xor_sync(~0u, p0B, o);
            p1B += __shfl_xor_sync(~0u, p1B, o);
        }
        if (lx == 0) {
            size_t base = (size_t)(b*SS + i)*SS;
            g_P0[base + jA] = p0A;
            g_P1[base + jA] = p1A;
            g_P0[base + jB] = p0B;
            g_P1[base + jB] = p1B;
        }
    }
}

// ============================================================
// Kernel 3: logits + softmax + AV. One block per (b, i).
// ============================================================
__global__ void attn_kernel(const float* __restrict__ b3, const float* __restrict__ v,
                            float* __restrict__ out) {
    int i = blockIdx.x, b = blockIdx.y;
    int tid = threadIdx.x;   // = j
    int wid = tid >> 5, lane = tid & 31;
    __shared__ float wred[8];
    __shared__ float attn_s[256];
    __shared__ float red[1024];   // [grp 16][t 64]

    float logit = (b3[0] + g_P0[(size_t)(b*SS + i)*SS + tid]
                         + g_P1[(size_t)(b*SS + i + 1)*SS + tid]) * TEMP_INV;

    float m = logit;
    #pragma unroll
    for (int o = 16; o > 0; o >>= 1) m = fmaxf(m, __shfl_xor_sync(~0u, m, o));
    if (lane == 0) wred[wid] = m;
    __syncthreads();
    float mx = wred[0];
    #pragma unroll
    for (int w = 1; w < 8; w++) mx = fmaxf(mx, wred[w]);

    float p = __expf(logit - mx);
    float s = p;
    #pragma unroll
    for (int o = 16; o > 0; o >>= 1) s += __shfl_xor_sync(~0u, s, o);
    __syncthreads();
    if (lane == 0) wred[wid] = s;
    __syncthreads();
    float tot = wred[0];
    #pragma unroll
    for (int w = 1; w < 8; w++) tot += wred[w];
    float inv = 1.f / tot;

    float a = p * inv;
    attn_s[tid] = a;
    out[(size_t)BB*SO*DIMQ + (size_t)(b*SO + i)*SS + tid] = a;
    __syncthreads();

    int t4 = tid & 15, grp = tid >> 4;
    const float* vb = v + (size_t)b*SS*DIMQ;
    float4 acc = make_float4(0.f, 0.f, 0.f, 0.f);
    #pragma unroll 4
    for (int jj = 0; jj < 16; jj++) {
        int j = grp*16 + jj;
        float aw = attn_s[j];
        float4 v4 = *(const float4*)(vb + (size_t)j*DIMQ + t4*4);
        acc.x = fmaf(aw, v4.x, acc.x);
        acc.y = fmaf(aw, v4.y, acc.y);
        acc.z = fmaf(aw, v4.z, acc.z);
        acc.w = fmaf(aw, v4.w, acc.w);
    }
    *(float4*)(red + grp*64 + t4*4) = acc;
    __syncthreads();
    if (tid < 64) {
        float o = 0.f;
        #pragma unroll
        for (int g = 0; g < 16; g++) o += red[g*64 + tid];
        out[(size_t)(b*SO + i)*DIMQ + tid] = o;
    }
}

// ============================================================
extern "C" void kernel_launch(void* const* d_in, const int* in_sizes, int n_in,
                              void* d_out, int out_size) {
    const float* q    = (const float*)d_in[0];
    const float* k    = (const float*)d_in[1];
    const float* v    = (const float*)d_in[2];
    const float* W1   = (const float*)d_in[3];
    const float* b1   = (const float*)d_in[4];
    const float* g1   = (const float*)d_in[5];
    const float* be1  = (const float*)d_in[6];
    const float* m1   = (const float*)d_in[7];
    const float* var1 = (const float*)d_in[8];
    const float* W2   = (const float*)d_in[9];
    const float* b2   = (const float*)d_in[10];
    const float* g2   = (const float*)d_in[11];
    const float* be2  = (const float*)d_in[12];
    const float* m2   = (const float*)d_in[13];
    const float* var2 = (const float*)d_in[14];
    const float* W3   = (const float*)d_in[15];
    const float* b3   = (const float*)d_in[16];
    float* out = (float*)d_out;

    cudaFuncSetAttribute(gemm2_mma, cudaFuncAttributeMaxDynamicSharedMemorySize,
                         SM_WORDS * (int)sizeof(float));

    params_kernel<<<1, 256>>>(W1, b1, b2, g1, be1, m1, var1, g2, be2, m2, var2);
    quantW2_kernel<<<NPAD, 64>>>(W2);
    prep_kernel  <<<dim3((SS*DD + 255)/256, BB, 2), 256>>>(q, k);
    gemm2_mma    <<<dim3(2, SA, BB), 256, SM_WORDS*sizeof(float)>>>(b1, W3);
    attn_kernel  <<<dim3(SO, BB), 256>>>(b3, v, out);
}